// round 7
// baseline (speedup 1.0000x reference)
#include <cuda_runtime.h>
#include <cuda_fp16.h>
#include <cstdint>

#define BATCH 64
#define NB    64
#define RANK  4
#define SEQ   4096

// sqrt(log2(e)) — folds natural-exp into a single ex2.approx
#define SQRT_LOG2E 1.2011224087864498f

#define NBLK 148           // persistent grid (all resident; <= SM count)
#define NA   32            // MLP blocks
#define NH   (NBLK - NA)   // basis/h_t blocks = 116

#define KS2 4              // split-K, layer 2
#define KS3 8              // split-K, layer 3
#define OMSZ (BATCH * NB * RANK * 2)     // floats per omega partial

// ---------------------------------------------------------------------------
// Scratch (device globals; no allocation allowed)
// ---------------------------------------------------------------------------
__device__ __align__(16) float    g_h1 [BATCH * 512];          // relu(f@W1+b1) final
__device__ __align__(16) float    g_h2p[KS2 * BATCH * 1024];   // layer-2 partials
__device__ __align__(16) float    g_omp[KS3 * OMSZ];           // packed omega partials
__device__ __align__(16) float2   g_oms[BATCH * NB * RANK];    // final omega (even,odd)
__device__ __align__(16) unsigned g_ht [BATCH * SEQ * NB / 2]; // h_t fp16x2 words, 32 MB
__device__ unsigned g_bars[4];                                  // monotonic barrier ctrs

// ---------------------------------------------------------------------------
// Replay-safe monotonic barrier: each use consumes exactly P increments, so
// the counter stays aligned to multiples of P across graph replays (never
// reset). Requires all participating blocks resident (guaranteed: grid=148,
// __launch_bounds__(256,2) => >=2 blocks/SM capacity).
// ---------------------------------------------------------------------------
__device__ __forceinline__ void sysbar(int i, unsigned P)
{
    __syncthreads();
    if (threadIdx.x == 0) {
        __threadfence();
        const unsigned old = atomicAdd(&g_bars[i], 1u);
        const unsigned target = old - (old % P) + P;
        while (*((volatile unsigned*)&g_bars[i]) < target) __nanosleep(32);
        __threadfence();
    }
    __syncthreads();
}

// ---------------------------------------------------------------------------
// One GEMM tile: 64 batch rows x 64 cols, k-range = K/KS starting at z*KC.
// 256 threads: tid<128 stage W, tid>=128 stage A; compute as 16x16 thread
// grid, 4 rows x 4 cols each, f32x2 packed accumulators. Depth-3 register
// prefetch over double-buffered smem (one barrier per 8-k chunk).
// SRC: 0 = Ain param, 1 = g_h1 (final), 2 = sum NPART g_h2p partials + relu
// DST: 0 = g_h1 final (+bias+relu), 1 = g_h2p[z], 2 = packed omega partial
// ---------------------------------------------------------------------------
template <int K, int N, int KS, int SRC, int NPART, int DST>
__device__ __forceinline__ void gemm_tile(
    float (&sW)[2][8][64], float (&sA)[2][8][64],
    const float* __restrict__ Ain, const float* __restrict__ W,
    const float* __restrict__ bias, int j0, int z)
{
    constexpr int KC  = K / KS;
    constexpr int NCH = KC / 8;
    const int tid = threadIdx.x;
    const int tx  = tid & 15;
    const int ty  = tid >> 4;
    const int k0  = z * KC;

    const bool isW = tid < 128;
    const int w_kk = tid >> 4;
    const int w_c4 = (tid & 15) * 4;
    const int a_i  = tid - 128;
    const int a_b  = a_i >> 1;
    const int a_kq = (a_i & 1) * 4;

    auto load_chunk = [&](int kc) -> float4 {
        if (isW)
            return *(const float4*)(W + (size_t)(k0 + kc + w_kk) * N + j0 + w_c4);
        float4 av;
        if (SRC == 0) {
            av = *(const float4*)(Ain + a_b * K + k0 + kc + a_kq);
        } else if (SRC == 1) {
            av = *(const float4*)(g_h1 + a_b * K + k0 + kc + a_kq);
        } else {
            const float* p0 = g_h2p + a_b * K + k0 + kc + a_kq;
            av = *(const float4*)p0;
            #pragma unroll
            for (int p = 1; p < NPART; p++) {
                const float4 v = *(const float4*)(p0 + p * (BATCH * K));
                av.x += v.x; av.y += v.y; av.z += v.z; av.w += v.w;
            }
            av.x = fmaxf(av.x, 0.f); av.y = fmaxf(av.y, 0.f);
            av.z = fmaxf(av.z, 0.f); av.w = fmaxf(av.w, 0.f);
        }
        return av;
    };
    auto store_chunk = [&](int buf, float4 v) {
        if (isW) {
            *(float4*)(&sW[buf][w_kk][w_c4]) = v;
        } else {
            sA[buf][a_kq + 0][a_b] = v.x;
            sA[buf][a_kq + 1][a_b] = v.y;
            sA[buf][a_kq + 2][a_b] = v.z;
            sA[buf][a_kq + 3][a_b] = v.w;
        }
    };

    unsigned long long acc2[4][2];
    #pragma unroll
    for (int r = 0; r < 4; r++) { acc2[r][0] = 0ull; acc2[r][1] = 0ull; }

    // depth-3 pipeline: f1 = chunk c+1 (awaiting store), f2 = c+2, f3 = c+3
    float4 f0 = load_chunk(0);
    store_chunk(0, f0);
    float4 f1 = load_chunk(8);
    float4 f2 = load_chunk(16);
    __syncthreads();

    for (int c = 0; c < NCH; c++) {
        float4 f3;
        if (c + 3 < NCH) f3 = load_chunk((c + 3) * 8);

        const int buf = c & 1;
        #pragma unroll
        for (int kk = 0; kk < 8; kk++) {
            const ulonglong2 wq = *(const ulonglong2*)(&sW[buf][kk][tx * 4]);
            const float4 av = *(const float4*)(&sA[buf][kk][ty * 4]);
            const float aa[4] = {av.x, av.y, av.z, av.w};
            #pragma unroll
            for (int r = 0; r < 4; r++) {
                unsigned long long ap;
                asm("mov.b64 %0, {%1, %1};" : "=l"(ap) : "f"(aa[r]));
                asm("fma.rn.f32x2 %0, %1, %2, %0;"
                    : "+l"(acc2[r][0]) : "l"(ap), "l"(wq.x));
                asm("fma.rn.f32x2 %0, %1, %2, %0;"
                    : "+l"(acc2[r][1]) : "l"(ap), "l"(wq.y));
            }
        }

        if (c + 1 < NCH) store_chunk((c + 1) & 1, f1);
        __syncthreads();
        f1 = f2; f2 = f3;
    }

    // epilogue
    float o[4][4];
    #pragma unroll
    for (int r = 0; r < 4; r++) {
        asm("mov.b64 {%0, %1}, %2;" : "=f"(o[r][0]), "=f"(o[r][1]) : "l"(acc2[r][0]));
        asm("mov.b64 {%0, %1}, %2;" : "=f"(o[r][2]), "=f"(o[r][3]) : "l"(acc2[r][1]));
    }
    const int j = j0 + tx * 4;
    if (z == 0) {
        const float4 bv = *(const float4*)(bias + j);
        #pragma unroll
        for (int r = 0; r < 4; r++) {
            o[r][0] += bv.x; o[r][1] += bv.y; o[r][2] += bv.z; o[r][3] += bv.w;
        }
    }
    #pragma unroll
    for (int r = 0; r < 4; r++) {
        const int bb = ty * 4 + r;
        if (DST == 0) {
            *(float4*)(g_h1 + bb * 512 + j) = make_float4(
                fmaxf(o[r][0], 0.f), fmaxf(o[r][1], 0.f),
                fmaxf(o[r][2], 0.f), fmaxf(o[r][3], 0.f));
        } else if (DST == 1) {
            *(float4*)(g_h2p + z * (BATCH * 1024) + bb * 1024 + j) =
                make_float4(o[r][0], o[r][1], o[r][2], o[r][3]);
        } else {
            const int side = (j >= 256) ? 1 : 0;
            const int n    = (j - side * 256) >> 2;
            float* dst = g_omp + z * OMSZ + ((bb * NB + n) * RANK) * 2 + side;
            dst[0] = o[r][0]; dst[2] = o[r][1];
            dst[4] = o[r][2]; dst[6] = o[r][3];
        }
    }
}

// ---------------------------------------------------------------------------
// h_t evaluation: one fused fma.rn.f32x2 gives {u, w}; ex2 + cos + mul.
// s_bp layout per n: float4(a2, beta, -a2*mu, gamma) so q.x={a2,beta},
// q.y={-a2mu,gamma}; {t,t}*q.x+q.y = {u, w}.
// ---------------------------------------------------------------------------
__device__ __forceinline__ float ht_eval(unsigned long long tp, ulonglong2 q)
{
    unsigned long long uw;
    asm("fma.rn.f32x2 %0, %1, %2, %3;" : "=l"(uw) : "l"(tp), "l"(q.x), "l"(q.y));
    float u, w;
    asm("mov.b64 {%0, %1}, %2;" : "=f"(u), "=f"(w) : "l"(uw));
    const float nv = -u * u;
    float e, c;
    asm("ex2.approx.f32 %0, %1;" : "=f"(e) : "f"(nv));
    asm("cos.approx.f32 %0, %1;" : "=f"(c) : "f"(w));
    return e * c;
}

// compute h_t for points (b,s) and (b,s+256), store fp16 rows to g_ht
__device__ __forceinline__ void ht_pair(const float* __restrict__ t,
                                        const float4* s_bp, int b, int s)
{
    const float tv0 = t[b * SEQ + s];
    const float tv1 = t[b * SEQ + s + 256];
    unsigned long long tp0, tp1;
    asm("mov.b64 %0, {%1, %1};" : "=l"(tp0) : "f"(tv0));
    asm("mov.b64 %0, {%1, %1};" : "=l"(tp1) : "f"(tv1));

    uint4* row0 = (uint4*)(g_ht + (size_t)(b * SEQ + s) * 32);
    uint4* row1 = (uint4*)(g_ht + (size_t)(b * SEQ + s + 256) * 32);
    const ulonglong2* bq = (const ulonglong2*)s_bp;

    #pragma unroll
    for (int g = 0; g < 8; g++) {
        unsigned w0[4], w1[4];
        #pragma unroll
        for (int wi = 0; wi < 4; wi++) {
            float h0[2], h1[2];
            #pragma unroll
            for (int e = 0; e < 2; e++) {
                const ulonglong2 q = bq[g * 8 + wi * 2 + e];
                h0[e] = ht_eval(tp0, q);
                h1[e] = ht_eval(tp1, q);
            }
            __half2 p0 = __floats2half2_rn(h0[0], h0[1]);
            __half2 p1 = __floats2half2_rn(h1[0], h1[1]);
            w0[wi] = *(unsigned*)&p0;
            w1[wi] = *(unsigned*)&p1;
        }
        row0[g] = make_uint4(w0[0], w0[1], w0[2], w0[3]);
        row1[g] = make_uint4(w1[0], w1[1], w1[2], w1[3]);
    }
}

// ---------------------------------------------------------------------------
// Phase B: out rows for points (b,s) and (b,s+256): read fp16 h rows,
// accumulate (even,odd) per rank with fma.rn.f32x2 against s_om.
// ---------------------------------------------------------------------------
__device__ __forceinline__ void fin_pair(float* __restrict__ out,
                                         const float2* s_om, int b, int s)
{
    const uint4* r0 = (const uint4*)(g_ht + (size_t)(b * SEQ + s) * 32);
    const uint4* r1 = (const uint4*)(g_ht + (size_t)(b * SEQ + s + 256) * 32);
    const unsigned long long* omq = (const unsigned long long*)s_om;

    unsigned long long acc0[4] = {0ull, 0ull, 0ull, 0ull};
    unsigned long long acc1[4] = {0ull, 0ull, 0ull, 0ull};

    #pragma unroll
    for (int g = 0; g < 8; g++) {
        const uint4 hv0 = r0[g];
        const uint4 hv1 = r1[g];
        const unsigned hw0[4] = {hv0.x, hv0.y, hv0.z, hv0.w};
        const unsigned hw1[4] = {hv1.x, hv1.y, hv1.z, hv1.w};
        #pragma unroll
        for (int wi = 0; wi < 4; wi++) {
            const int n0 = g * 8 + wi * 2;
            const ulonglong2 qa = *(const ulonglong2*)(omq + n0 * 4);
            const ulonglong2 qb = *(const ulonglong2*)(omq + n0 * 4 + 2);
            const ulonglong2 qc = *(const ulonglong2*)(omq + n0 * 4 + 4);
            const ulonglong2 qd = *(const ulonglong2*)(omq + n0 * 4 + 6);
            const float2 f0 = __half22float2(*(const __half2*)&hw0[wi]);
            const float2 f1 = __half22float2(*(const __half2*)&hw1[wi]);
            unsigned long long p;
            asm("mov.b64 %0, {%1, %1};" : "=l"(p) : "f"(f0.x));
            asm("fma.rn.f32x2 %0, %1, %2, %0;" : "+l"(acc0[0]) : "l"(p), "l"(qa.x));
            asm("fma.rn.f32x2 %0, %1, %2, %0;" : "+l"(acc0[1]) : "l"(p), "l"(qa.y));
            asm("fma.rn.f32x2 %0, %1, %2, %0;" : "+l"(acc0[2]) : "l"(p), "l"(qb.x));
            asm("fma.rn.f32x2 %0, %1, %2, %0;" : "+l"(acc0[3]) : "l"(p), "l"(qb.y));
            asm("mov.b64 %0, {%1, %1};" : "=l"(p) : "f"(f0.y));
            asm("fma.rn.f32x2 %0, %1, %2, %0;" : "+l"(acc0[0]) : "l"(p), "l"(qc.x));
            asm("fma.rn.f32x2 %0, %1, %2, %0;" : "+l"(acc0[1]) : "l"(p), "l"(qc.y));
            asm("fma.rn.f32x2 %0, %1, %2, %0;" : "+l"(acc0[2]) : "l"(p), "l"(qd.x));
            asm("fma.rn.f32x2 %0, %1, %2, %0;" : "+l"(acc0[3]) : "l"(p), "l"(qd.y));
            asm("mov.b64 %0, {%1, %1};" : "=l"(p) : "f"(f1.x));
            asm("fma.rn.f32x2 %0, %1, %2, %0;" : "+l"(acc1[0]) : "l"(p), "l"(qa.x));
            asm("fma.rn.f32x2 %0, %1, %2, %0;" : "+l"(acc1[1]) : "l"(p), "l"(qa.y));
            asm("fma.rn.f32x2 %0, %1, %2, %0;" : "+l"(acc1[2]) : "l"(p), "l"(qb.x));
            asm("fma.rn.f32x2 %0, %1, %2, %0;" : "+l"(acc1[3]) : "l"(p), "l"(qb.y));
            asm("mov.b64 %0, {%1, %1};" : "=l"(p) : "f"(f1.y));
            asm("fma.rn.f32x2 %0, %1, %2, %0;" : "+l"(acc1[0]) : "l"(p), "l"(qc.x));
            asm("fma.rn.f32x2 %0, %1, %2, %0;" : "+l"(acc1[1]) : "l"(p), "l"(qc.y));
            asm("fma.rn.f32x2 %0, %1, %2, %0;" : "+l"(acc1[2]) : "l"(p), "l"(qd.x));
            asm("fma.rn.f32x2 %0, %1, %2, %0;" : "+l"(acc1[3]) : "l"(p), "l"(qd.y));
        }
    }

    float* ob = out + (size_t)b * (2 * SEQ * RANK);
    {
        float ev[4], od[4];
        #pragma unroll
        for (int r = 0; r < 4; r++)
            asm("mov.b64 {%0, %1}, %2;" : "=f"(ev[r]), "=f"(od[r]) : "l"(acc0[r]));
        float4* op = (float4*)(ob + (size_t)s * 8);
        op[0] = make_float4(ev[0], ev[1], ev[2], ev[3]);
        op[1] = make_float4(od[0], od[1], od[2], od[3]);
    }
    {
        float ev[4], od[4];
        #pragma unroll
        for (int r = 0; r < 4; r++)
            asm("mov.b64 {%0, %1}, %2;" : "=f"(ev[r]), "=f"(od[r]) : "l"(acc1[r]));
        float4* op = (float4*)(ob + (size_t)(s + 256) * 8);
        op[0] = make_float4(ev[0], ev[1], ev[2], ev[3]);
        op[1] = make_float4(od[0], od[1], od[2], od[3]);
    }
}

// ---------------------------------------------------------------------------
// Persistent mega-kernel
// ---------------------------------------------------------------------------
__global__ void __launch_bounds__(256, 2)
mega_kernel(const float* __restrict__ f,  const float* __restrict__ t,
            const float* __restrict__ W1, const float* __restrict__ b1,
            const float* __restrict__ W2, const float* __restrict__ b2,
            const float* __restrict__ W3, const float* __restrict__ b3,
            const float* __restrict__ mu, const float* __restrict__ alpha,
            const float* __restrict__ beta, const float* __restrict__ gamma,
            float* __restrict__ out)
{
    __shared__ __align__(16) float  sW[2][8][64];
    __shared__ __align__(16) float  sA[2][8][64];
    __shared__ __align__(16) float4 s_bp[NB];
    __shared__ __align__(16) float2 s_om[NB * RANK];

    const int bid = blockIdx.x;
    const int tid = threadIdx.x;

    if (bid < NA) {
        // ---------------- MLP group ----------------
        for (int tile = bid; tile < 8; tile += NA)
            gemm_tile<128, 512, 1, 0, 1, 0>(sW, sA, f, W1, b1, tile * 64, 0);
        sysbar(0, NA);
        for (int tile = bid; tile < 64; tile += NA)
            gemm_tile<512, 1024, KS2, 1, 1, 1>(sW, sA, nullptr, W2, b2,
                                               (tile & 15) * 64, tile >> 4);
        sysbar(1, NA);
        for (int tile = bid; tile < 64; tile += NA)
            gemm_tile<1024, 512, KS3, 2, KS2, 2>(sW, sA, nullptr, W3, b3,
                                                 (tile & 7) * 64, tile >> 3);
        sysbar(2, NA);
        {   // omega reduce: 8192 float4 over exactly NA*256 = 8192 threads
            const float4* src = (const float4*)g_omp;
            float4* dst = (float4*)g_oms;
            const int e = bid * 256 + tid;
            float4 a = src[e];
            #pragma unroll
            for (int p = 1; p < KS3; p++) {
                const float4 v = src[p * (OMSZ / 4) + e];
                a.x += v.x; a.y += v.y; a.z += v.z; a.w += v.w;
            }
            dst[e] = a;
        }
    } else {
        // ---------------- h_t group ----------------
        if (tid < NB) {
            const float a2 = alpha[tid] * SQRT_LOG2E;
            s_bp[tid] = make_float4(a2, beta[tid], -a2 * mu[tid], gamma[tid]);
        }
        __syncthreads();
        for (int tile = bid - NA; tile < 512; tile += NH) {
            const int b = tile >> 3;
            const int s = ((tile & 7) << 9) + tid;   // this thread: s and s+256
            ht_pair(t, s_bp, b, s);
        }
    }

    sysbar(3, NBLK);   // omega + h_t both globally visible

    // ---------------- Phase B: all blocks ----------------
    for (int tile = bid; tile < 512; tile += NBLK) {
        const int b = tile >> 3;
        const int s = ((tile & 7) << 9) + tid;
        __syncthreads();                       // prior tile done with s_om
        s_om[tid] = g_oms[b * 256 + tid];      // 256 float2 = omega[b]
        __syncthreads();
        fin_pair(out, s_om, b, s);
    }
}

// ---------------------------------------------------------------------------
// Launch: one plain kernel launch (graph-capturable)
// ---------------------------------------------------------------------------
extern "C" void kernel_launch(void* const* d_in, const int* in_sizes, int n_in,
                              void* d_out, int out_size)
{
    const float* f     = (const float*)d_in[0];
    const float* t     = (const float*)d_in[1];
    const float* W1    = (const float*)d_in[2];
    const float* b1    = (const float*)d_in[3];
    const float* W2    = (const float*)d_in[4];
    const float* b2    = (const float*)d_in[5];
    const float* W3    = (const float*)d_in[6];
    const float* b3    = (const float*)d_in[7];
    const float* mu    = (const float*)d_in[8];
    const float* alpha = (const float*)d_in[9];
    const float* beta  = (const float*)d_in[10];
    const float* gamma = (const float*)d_in[11];
    float* out = (float*)d_out;

    mega_kernel<<<NBLK, 256>>>(f, t, W1, b1, W2, b2, W3, b3,
                               mu, alpha, beta, gamma, out);
}

// round 8
// speedup vs baseline: 1.9307x; 1.9307x over previous
#include <cuda_runtime.h>
#include <cuda_fp16.h>
#include <cstdint>

#define BATCH 64
#define NB    64
#define RANK  4
#define SEQ   4096

// sqrt(log2(e)) — folds natural-exp into a single ex2.approx
#define SQRT_LOG2E 1.2011224087864498f

#define KS1 4    // split-K, layer 1
#define KS2 8    // split-K, layer 2
#define KS3 16   // split-K, layer 3
#define OMSZ (BATCH * NB * RANK * 2)   // floats per omega partial (32768)

// ---------------------------------------------------------------------------
// Scratch (device globals; no allocation allowed)
// ---------------------------------------------------------------------------
__device__ float g_h1p[KS1 * BATCH * 512];     // pre-relu partials of layer 1
__device__ float g_h2p[KS2 * BATCH * 1024];    // pre-relu partials of layer 2
__device__ float g_om [KS3 * OMSZ];            // packed omega partials
// omega packing within one partial: [((b*NB+n)*RANK+r)*2 + side]

// ---------------------------------------------------------------------------
// Tiled GEMM (R5 winner): block tile = 64 batch rows x 64 cols; 256 threads
// = 16 tx (4 cols) x 16 ty (4 rows); accumulators = 8 packed f32x2.
// Depth-2 register prefetch over double-buffered 8-k smem chunks.
// Split-K via blockIdx.z -> disjoint partials (bias only in split 0);
// A-staging threads sum the producer's NPART partials (+relu) inline.
// SRC: 0 = Ain param, 1 = g_h1p, 2 = g_h2p
// DST: 0 = g_h1p partial, 1 = g_h2p partial, 2 = packed omega partial
// ---------------------------------------------------------------------------
template <int K, int N, int KS, int SRC, int NPART, int DST>
__global__ __launch_bounds__(256)
void gemm_tiled(const float* __restrict__ Ain,
                const float* __restrict__ W,
                const float* __restrict__ bias)
{
    constexpr int KC  = K / KS;
    constexpr int NCH = KC / 8;

    __shared__ __align__(16) float sW[2][8][64];
    __shared__ __align__(16) float sA[2][8][64];

    const int tid = threadIdx.x;
    const int tx  = tid & 15;
    const int ty  = tid >> 4;
    const int j0  = blockIdx.x * 64;
    const int z   = blockIdx.z;
    const int k0  = z * KC;

    const bool isW = tid < 128;
    const int w_kk = tid >> 4;
    const int w_c4 = (tid & 15) * 4;
    const int a_i  = tid - 128;
    const int a_b  = a_i >> 1;
    const int a_kq = (a_i & 1) * 4;

    auto load_chunk = [&](int kc) -> float4 {
        if (isW)
            return *(const float4*)(W + (size_t)(k0 + kc + w_kk) * N + j0 + w_c4);
        float4 av;
        if (SRC == 0) {
            av = *(const float4*)(Ain + a_b * K + k0 + kc + a_kq);
        } else {
            const float* base = (SRC == 1) ? g_h1p : g_h2p;
            const float* p0 = base + a_b * K + k0 + kc + a_kq;
            av = *(const float4*)p0;
            #pragma unroll
            for (int p = 1; p < NPART; p++) {
                const float4 pv = *(const float4*)(p0 + p * (BATCH * K));
                av.x += pv.x; av.y += pv.y; av.z += pv.z; av.w += pv.w;
            }
            av.x = fmaxf(av.x, 0.f); av.y = fmaxf(av.y, 0.f);
            av.z = fmaxf(av.z, 0.f); av.w = fmaxf(av.w, 0.f);
        }
        return av;
    };
    auto store_chunk = [&](int buf, float4 v) {
        if (isW) {
            *(float4*)(&sW[buf][w_kk][w_c4]) = v;
        } else {
            sA[buf][a_kq + 0][a_b] = v.x;
            sA[buf][a_kq + 1][a_b] = v.y;
            sA[buf][a_kq + 2][a_b] = v.z;
            sA[buf][a_kq + 3][a_b] = v.w;
        }
    };

    unsigned long long acc2[4][2];
    #pragma unroll
    for (int r = 0; r < 4; r++) { acc2[r][0] = 0ull; acc2[r][1] = 0ull; }

    float4 f0 = load_chunk(0);
    store_chunk(0, f0);
    float4 f1;
    if (NCH > 1) f1 = load_chunk(8);
    __syncthreads();

    for (int c = 0; c < NCH; c++) {
        float4 f2;
        if (c + 2 < NCH) f2 = load_chunk((c + 2) * 8);

        const int buf = c & 1;
        #pragma unroll
        for (int kk = 0; kk < 8; kk++) {
            const ulonglong2 wq = *(const ulonglong2*)(&sW[buf][kk][tx * 4]);
            const float4 av = *(const float4*)(&sA[buf][kk][ty * 4]);
            const float aa[4] = {av.x, av.y, av.z, av.w};
            #pragma unroll
            for (int r = 0; r < 4; r++) {
                unsigned long long ap;
                asm("mov.b64 %0, {%1, %1};" : "=l"(ap) : "f"(aa[r]));
                asm("fma.rn.f32x2 %0, %1, %2, %0;"
                    : "+l"(acc2[r][0]) : "l"(ap), "l"(wq.x));
                asm("fma.rn.f32x2 %0, %1, %2, %0;"
                    : "+l"(acc2[r][1]) : "l"(ap), "l"(wq.y));
            }
        }

        if (c + 1 < NCH) store_chunk((c + 1) & 1, f1);
        __syncthreads();
        f1 = f2;
    }

    float o[4][4];
    #pragma unroll
    for (int r = 0; r < 4; r++) {
        asm("mov.b64 {%0, %1}, %2;" : "=f"(o[r][0]), "=f"(o[r][1]) : "l"(acc2[r][0]));
        asm("mov.b64 {%0, %1}, %2;" : "=f"(o[r][2]), "=f"(o[r][3]) : "l"(acc2[r][1]));
    }
    const int j = j0 + tx * 4;
    if (z == 0) {
        const float4 bv = *(const float4*)(bias + j);
        #pragma unroll
        for (int r = 0; r < 4; r++) {
            o[r][0] += bv.x; o[r][1] += bv.y; o[r][2] += bv.z; o[r][3] += bv.w;
        }
    }
    #pragma unroll
    for (int r = 0; r < 4; r++) {
        const int b = ty * 4 + r;
        if (DST == 0) {
            *(float4*)(g_h1p + z * (BATCH * 512) + b * 512 + j) =
                make_float4(o[r][0], o[r][1], o[r][2], o[r][3]);
        } else if (DST == 1) {
            *(float4*)(g_h2p + z * (BATCH * 1024) + b * 1024 + j) =
                make_float4(o[r][0], o[r][1], o[r][2], o[r][3]);
        } else {
            const int side = (j >= 256) ? 1 : 0;
            const int n    = (j - side * 256) >> 2;
            float* dst = g_om + z * OMSZ + ((b * NB + n) * RANK) * 2 + side;
            dst[0] = o[r][0]; dst[2] = o[r][1];
            dst[4] = o[r][2]; dst[6] = o[r][3];
        }
    }
}

// ---------------------------------------------------------------------------
// h_t evaluation: one fma.rn.f32x2 gives {u, w}, then ex2 + cos + mul.
// s_bp per n: float4(a2, beta, -a2*mu, gamma) -> q.x={a2,beta},
// q.y={-a2mu,gamma}; {t,t}*q.x + q.y = {u, w}.
// ---------------------------------------------------------------------------
__device__ __forceinline__ float ht_eval(unsigned long long tp, ulonglong2 q)
{
    unsigned long long uw;
    asm("fma.rn.f32x2 %0, %1, %2, %3;" : "=l"(uw) : "l"(tp), "l"(q.x), "l"(q.y));
    float u, w;
    asm("mov.b64 {%0, %1}, %2;" : "=f"(u), "=f"(w) : "l"(uw));
    const float nv = -u * u;
    float e, c;
    asm("ex2.approx.f32 %0, %1;" : "=f"(e) : "f"(nv));
    asm("cos.approx.f32 %0, %1;" : "=f"(c) : "f"(w));
    return e * c;
}

// ---------------------------------------------------------------------------
// Basis + projection via tensor cores. grid(32, BATCH), 256 threads = 8
// warps; each warp owns one 16-seq-row tile: lanes compute h_t (fp32 math,
// fp16 pack) directly in m16n8k16 A-fragment layout; omega (fp16 hi+lo
// split => fp32-accurate) is the B operand; 8 MMAs produce the 16x8 fp32
// output tile = interleaved (even,odd) x rank rows.
// ---------------------------------------------------------------------------
__global__ __launch_bounds__(256)
void basis_mma(const float* __restrict__ t,
               const float* __restrict__ mu,
               const float* __restrict__ alpha,
               const float* __restrict__ beta,
               const float* __restrict__ gamma,
               float* __restrict__ out)
{
    __shared__ __align__(16) float4 s_bp[NB];      // (a2, beta, -a2*mu, gamma)
    __shared__ __align__(16) float2 s_om[NB * RANK]; // (even, odd) per (n, r)

    const int tid  = threadIdx.x;
    const int b    = blockIdx.y;
    const int warp = tid >> 5;
    const int lane = tid & 31;
    const int gid  = lane >> 2;   // 0..7
    const int tig  = lane & 3;    // 0..3

    if (tid < NB) {
        const float a2 = alpha[tid] * SQRT_LOG2E;
        s_bp[tid] = make_float4(a2, beta[tid], -a2 * mu[tid], gamma[tid]);
    }
    {   // omega: sum KS3 partials; 256 threads x 1 float2 each
        const float2* src = (const float2*)(g_om + b * (NB * RANK * 2));
        float2 acc = src[tid];
        #pragma unroll
        for (int p = 1; p < KS3; p++) {
            const float2 pv = src[p * (OMSZ / 2) + tid];
            acc.x += pv.x; acc.y += pv.y;
        }
        s_om[tid] = acc;
    }
    __syncthreads();

    // Omega element: matrix col c in [0,8): c<4 -> even rank c, c>=4 -> odd.
    auto omega_at = [&](int k, int c) -> float {
        const float2 v = s_om[k * 4 + (c & 3)];
        return (c < 4) ? v.x : v.y;
    };

    // Build B fragments (col = gid), hi + lo fp16 split of fp32 omega.
    unsigned bhi[4][2], blo[4][2];
    #pragma unroll
    for (int kc = 0; kc < 4; kc++) {
        #pragma unroll
        for (int h = 0; h < 2; h++) {
            const int k0 = kc * 16 + tig * 2 + h * 8;
            const float w0 = omega_at(k0, gid);
            const float w1 = omega_at(k0 + 1, gid);
            __half2 hh = __floats2half2_rn(w0, w1);
            const float2 hf = __half22float2(hh);
            __half2 ll = __floats2half2_rn(w0 - hf.x, w1 - hf.y);
            bhi[kc][h] = *(unsigned*)&hh;
            blo[kc][h] = *(unsigned*)&ll;
        }
    }

    // This warp's tile: 16 seq rows starting at s0.
    const int s0 = (blockIdx.x * 8 + warp) * 16;
    const int r0 = s0 + gid;
    const int r1 = r0 + 8;
    const float tv0 = t[(size_t)b * SEQ + r0];
    const float tv1 = t[(size_t)b * SEQ + r1];
    unsigned long long tp0, tp1;
    asm("mov.b64 %0, {%1, %1};" : "=l"(tp0) : "f"(tv0));
    asm("mov.b64 %0, {%1, %1};" : "=l"(tp1) : "f"(tv1));

    const ulonglong2* bq = (const ulonglong2*)s_bp;

    float c0 = 0.f, c1 = 0.f, c2 = 0.f, c3 = 0.f;

    #pragma unroll
    for (int kc = 0; kc < 4; kc++) {
        const int n0 = kc * 16 + tig * 2;
        // A fragment: a0={r0,n0..n0+1} a1={r1,n0..} a2={r0,n0+8..} a3={r1,n0+8..}
        const float e00 = ht_eval(tp0, bq[n0]);
        const float e01 = ht_eval(tp0, bq[n0 + 1]);
        const float e10 = ht_eval(tp1, bq[n0]);
        const float e11 = ht_eval(tp1, bq[n0 + 1]);
        const float e02 = ht_eval(tp0, bq[n0 + 8]);
        const float e03 = ht_eval(tp0, bq[n0 + 9]);
        const float e12 = ht_eval(tp1, bq[n0 + 8]);
        const float e13 = ht_eval(tp1, bq[n0 + 9]);
        __half2 A0 = __floats2half2_rn(e00, e01);
        __half2 A1 = __floats2half2_rn(e10, e11);
        __half2 A2 = __floats2half2_rn(e02, e03);
        __half2 A3 = __floats2half2_rn(e12, e13);
        const unsigned a0 = *(unsigned*)&A0, a1 = *(unsigned*)&A1;
        const unsigned a2 = *(unsigned*)&A2, a3 = *(unsigned*)&A3;

        asm("mma.sync.aligned.m16n8k16.row.col.f32.f16.f16.f32 "
            "{%0,%1,%2,%3}, {%4,%5,%6,%7}, {%8,%9}, {%0,%1,%2,%3};"
            : "+f"(c0), "+f"(c1), "+f"(c2), "+f"(c3)
            : "r"(a0), "r"(a1), "r"(a2), "r"(a3),
              "r"(bhi[kc][0]), "r"(bhi[kc][1]));
        asm("mma.sync.aligned.m16n8k16.row.col.f32.f16.f16.f32 "
            "{%0,%1,%2,%3}, {%4,%5,%6,%7}, {%8,%9}, {%0,%1,%2,%3};"
            : "+f"(c0), "+f"(c1), "+f"(c2), "+f"(c3)
            : "r"(a0), "r"(a1), "r"(a2), "r"(a3),
              "r"(blo[kc][0]), "r"(blo[kc][1]));
    }

    // C fragment: {c0,c1} -> row r0 cols tig*2,+1; {c2,c3} -> row r1.
    // out flat: b*32768 + s*8 + col  (col = side*4 + rank)
    float* ob = out + (size_t)b * (2 * SEQ * RANK);
    *(float2*)(ob + (size_t)r0 * 8 + tig * 2) = make_float2(c0, c1);
    *(float2*)(ob + (size_t)r1 * 8 + tig * 2) = make_float2(c2, c3);
}

// ---------------------------------------------------------------------------
// Launch
// ---------------------------------------------------------------------------
extern "C" void kernel_launch(void* const* d_in, const int* in_sizes, int n_in,
                              void* d_out, int out_size)
{
    const float* f     = (const float*)d_in[0];
    const float* t     = (const float*)d_in[1];
    const float* W1    = (const float*)d_in[2];
    const float* b1    = (const float*)d_in[3];
    const float* W2    = (const float*)d_in[4];
    const float* b2    = (const float*)d_in[5];
    const float* W3    = (const float*)d_in[6];
    const float* b3    = (const float*)d_in[7];
    const float* mu    = (const float*)d_in[8];
    const float* alpha = (const float*)d_in[9];
    const float* beta  = (const float*)d_in[10];
    const float* gamma = (const float*)d_in[11];
    float* out = (float*)d_out;

    // h1 partials = f @ W1 (+b1 in split 0)               [KS1][64, 512]
    gemm_tiled<128, 512, KS1, 0, 1, 0>
        <<<dim3(8, 1, KS1), 256>>>(f, W1, b1);
    // h2 partials = relu(sum h1p) @ W2 (+b2 in split 0)   [KS2][64, 1024]
    gemm_tiled<512, 1024, KS2, 1, KS1, 1>
        <<<dim3(16, 1, KS2), 256>>>(nullptr, W2, b2);
    // omega partials = relu(sum h2p) @ W3 (+b3)           [KS3][64, 512] packed
    gemm_tiled<1024, 512, KS3, 2, KS2, 2>
        <<<dim3(8, 1, KS3), 256>>>(nullptr, W3, b3);
    // basis + tensor-core projection
    basis_mma<<<dim3(32, BATCH), 256>>>(t, mu, alpha, beta, gamma, out);
}

// round 9
// speedup vs baseline: 1.9418x; 1.0057x over previous
#include <cuda_runtime.h>
#include <cuda_fp16.h>
#include <cstdint>

#define BATCH 64
#define NB    64
#define RANK  4
#define SEQ   4096

// sqrt(log2(e)) — folds natural-exp into a single ex2.approx
#define SQRT_LOG2E 1.2011224087864498f

#define NMLP  128            // MLP blocks (wave-1 resident, use barriers)
#define NHT   2048           // h_t blocks
#define NTILE 16384          // warp tiles: BATCH * SEQ/16

#define KS1 4
#define KS2 8
#define KS3 16
#define OMSZ (BATCH * NB * RANK * 2)   // floats per omega partial

// ---------------------------------------------------------------------------
// Scratch (device globals; no allocation allowed)
// ---------------------------------------------------------------------------
__device__ __align__(16) float  g_h1p[KS1 * BATCH * 512];
__device__ __align__(16) float  g_h2p[KS2 * BATCH * 1024];
__device__ __align__(16) float  g_omp[KS3 * OMSZ];
__device__ __align__(16) float2 g_oms[BATCH * NB * RANK];   // final omega
__device__ __align__(16) uint4  g_ht [NTILE * 128];         // h_t fragments, 32 MB
__device__ unsigned g_bars[4];                               // monotonic barriers

// ---------------------------------------------------------------------------
// Replay-safe monotonic barrier among P co-resident blocks (counter never
// reset; each use consumes exactly P increments, so replays stay aligned).
// ---------------------------------------------------------------------------
__device__ __forceinline__ void sysbar(int i, unsigned P)
{
    __syncthreads();
    if (threadIdx.x == 0) {
        __threadfence();
        const unsigned old = atomicAdd(&g_bars[i], 1u);
        const unsigned target = old - (old % P) + P;
        while (*((volatile unsigned*)&g_bars[i]) < target) __nanosleep(32);
        __threadfence();
    }
    __syncthreads();
}

// ---------------------------------------------------------------------------
// GEMM tile (R5-proven): 64 rows x 64 cols, 256 threads, f32x2 packed
// accumulators, depth-2 prefetch over double-buffered 8-k smem chunks.
// SRC: 0 = Ain param, 1 = g_h1p (sum NPART + relu), 2 = g_h2p (sum + relu)
// DST: 0 = g_h1p[z] (pre-relu), 1 = g_h2p[z], 2 = packed omega partial
// ---------------------------------------------------------------------------
template <int K, int N, int KS, int SRC, int NPART, int DST>
__device__ void gemm_tile(float (&sW)[2][8][64], float (&sA)[2][8][64],
                          const float* __restrict__ Ain,
                          const float* __restrict__ W,
                          const float* __restrict__ bias, int j0, int z)
{
    constexpr int KC  = K / KS;
    constexpr int NCH = KC / 8;
    const int tid = threadIdx.x;
    const int tx  = tid & 15;
    const int ty  = tid >> 4;
    const int k0  = z * KC;

    const bool isW = tid < 128;
    const int w_kk = tid >> 4;
    const int w_c4 = (tid & 15) * 4;
    const int a_i  = tid - 128;
    const int a_b  = a_i >> 1;
    const int a_kq = (a_i & 1) * 4;

    auto load_chunk = [&](int kc) -> float4 {
        if (isW)
            return *(const float4*)(W + (size_t)(k0 + kc + w_kk) * N + j0 + w_c4);
        float4 av;
        if (SRC == 0) {
            av = *(const float4*)(Ain + a_b * K + k0 + kc + a_kq);
        } else {
            const float* base = (SRC == 1) ? g_h1p : g_h2p;
            const float* p0 = base + a_b * K + k0 + kc + a_kq;
            av = *(const float4*)p0;
            #pragma unroll
            for (int p = 1; p < NPART; p++) {
                const float4 pv = *(const float4*)(p0 + p * (BATCH * K));
                av.x += pv.x; av.y += pv.y; av.z += pv.z; av.w += pv.w;
            }
            av.x = fmaxf(av.x, 0.f); av.y = fmaxf(av.y, 0.f);
            av.z = fmaxf(av.z, 0.f); av.w = fmaxf(av.w, 0.f);
        }
        return av;
    };
    auto store_chunk = [&](int buf, float4 v) {
        if (isW) {
            *(float4*)(&sW[buf][w_kk][w_c4]) = v;
        } else {
            sA[buf][a_kq + 0][a_b] = v.x;
            sA[buf][a_kq + 1][a_b] = v.y;
            sA[buf][a_kq + 2][a_b] = v.z;
            sA[buf][a_kq + 3][a_b] = v.w;
        }
    };

    unsigned long long acc2[4][2];
    #pragma unroll
    for (int r = 0; r < 4; r++) { acc2[r][0] = 0ull; acc2[r][1] = 0ull; }

    float4 f0 = load_chunk(0);
    store_chunk(0, f0);
    float4 f1;
    if (NCH > 1) f1 = load_chunk(8);
    __syncthreads();

    for (int c = 0; c < NCH; c++) {
        float4 f2;
        if (c + 2 < NCH) f2 = load_chunk((c + 2) * 8);

        const int buf = c & 1;
        #pragma unroll
        for (int kk = 0; kk < 8; kk++) {
            const ulonglong2 wq = *(const ulonglong2*)(&sW[buf][kk][tx * 4]);
            const float4 av = *(const float4*)(&sA[buf][kk][ty * 4]);
            const float aa[4] = {av.x, av.y, av.z, av.w};
            #pragma unroll
            for (int r = 0; r < 4; r++) {
                unsigned long long ap;
                asm("mov.b64 %0, {%1, %1};" : "=l"(ap) : "f"(aa[r]));
                asm("fma.rn.f32x2 %0, %1, %2, %0;"
                    : "+l"(acc2[r][0]) : "l"(ap), "l"(wq.x));
                asm("fma.rn.f32x2 %0, %1, %2, %0;"
                    : "+l"(acc2[r][1]) : "l"(ap), "l"(wq.y));
            }
        }

        if (c + 1 < NCH) store_chunk((c + 1) & 1, f1);
        __syncthreads();
        f1 = f2;
    }

    float o[4][4];
    #pragma unroll
    for (int r = 0; r < 4; r++) {
        asm("mov.b64 {%0, %1}, %2;" : "=f"(o[r][0]), "=f"(o[r][1]) : "l"(acc2[r][0]));
        asm("mov.b64 {%0, %1}, %2;" : "=f"(o[r][2]), "=f"(o[r][3]) : "l"(acc2[r][1]));
    }
    const int j = j0 + tx * 4;
    if (z == 0) {
        const float4 bv = *(const float4*)(bias + j);
        #pragma unroll
        for (int r = 0; r < 4; r++) {
            o[r][0] += bv.x; o[r][1] += bv.y; o[r][2] += bv.z; o[r][3] += bv.w;
        }
    }
    #pragma unroll
    for (int r = 0; r < 4; r++) {
        const int b = ty * 4 + r;
        if (DST == 0) {
            *(float4*)(g_h1p + z * (BATCH * 512) + b * 512 + j) =
                make_float4(o[r][0], o[r][1], o[r][2], o[r][3]);
        } else if (DST == 1) {
            *(float4*)(g_h2p + z * (BATCH * 1024) + b * 1024 + j) =
                make_float4(o[r][0], o[r][1], o[r][2], o[r][3]);
        } else {
            const int side = (j >= 256) ? 1 : 0;
            const int n    = (j - side * 256) >> 2;
            float* dst = g_omp + z * OMSZ + ((b * NB + n) * RANK) * 2 + side;
            dst[0] = o[r][0]; dst[2] = o[r][1];
            dst[4] = o[r][2]; dst[6] = o[r][3];
        }
    }
}

// ---------------------------------------------------------------------------
// h_t evaluation: one fma.rn.f32x2 gives {u, w}, then ex2 + cos + mul.
// s_bp per n: float4(a2, beta, -a2*mu, gamma).
// ---------------------------------------------------------------------------
__device__ __forceinline__ float ht_eval(unsigned long long tp, ulonglong2 q)
{
    unsigned long long uw;
    asm("fma.rn.f32x2 %0, %1, %2, %3;" : "=l"(uw) : "l"(tp), "l"(q.x), "l"(q.y));
    float u, w;
    asm("mov.b64 {%0, %1}, %2;" : "=f"(u), "=f"(w) : "l"(uw));
    const float nv = -u * u;
    float e, c;
    asm("ex2.approx.f32 %0, %1;" : "=f"(e) : "f"(nv));
    asm("cos.approx.f32 %0, %1;" : "=f"(c) : "f"(w));
    return e * c;
}

// ---------------------------------------------------------------------------
// Kernel A: fused MLP (blocks 0..NMLP-1, barrier-synced) + h_t fragment
// production (blocks NMLP.., fp16, MMA A-fragment order) — concurrent.
// ---------------------------------------------------------------------------
__global__ void __launch_bounds__(256, 2)
fused_a(const float* __restrict__ f,  const float* __restrict__ t,
        const float* __restrict__ W1, const float* __restrict__ b1,
        const float* __restrict__ W2, const float* __restrict__ b2,
        const float* __restrict__ W3, const float* __restrict__ b3,
        const float* __restrict__ mu, const float* __restrict__ alpha,
        const float* __restrict__ beta, const float* __restrict__ gamma)
{
    __shared__ __align__(16) float  sW[2][8][64];
    __shared__ __align__(16) float  sA[2][8][64];
    __shared__ __align__(16) float4 s_bp[NB];

    const int bid = blockIdx.x;
    const int tid = threadIdx.x;

    if (bid < NMLP) {
        // ---------------- fused MLP ----------------
        if (bid < 8 * KS1)   // 32 tiles: j0 x z
            gemm_tile<128, 512, KS1, 0, 1, 0>(sW, sA, f, W1, b1,
                                              (bid & 7) * 64, bid >> 3);
        sysbar(0, NMLP);
        // 16 col-tiles x KS2=8 = 128 units
        gemm_tile<512, 1024, KS2, 1, KS1, 1>(sW, sA, nullptr, W2, b2,
                                             (bid & 15) * 64, bid >> 4);
        sysbar(1, NMLP);
        // 8 col-tiles x KS3=16 = 128 units
        gemm_tile<1024, 512, KS3, 2, KS2, 2>(sW, sA, nullptr, W3, b3,
                                             (bid & 7) * 64, bid >> 3);
        sysbar(2, NMLP);
        if (bid < 32) {   // omega reduce: 8192 float4 over 32*256 threads
            const float4* src = (const float4*)g_omp;
            float4* dst = (float4*)g_oms;
            const int e = bid * 256 + tid;
            float4 a = src[e];
            #pragma unroll
            for (int p = 1; p < KS3; p++) {
                const float4 v = src[p * (OMSZ / 4) + e];
                a.x += v.x; a.y += v.y; a.z += v.z; a.w += v.w;
            }
            dst[e] = a;
        }
    } else {
        // ---------------- h_t fragments ----------------
        const int warp = tid >> 5;
        const int lane = tid & 31;
        const int gid  = lane >> 2;
        const int tig  = lane & 3;

        if (tid < NB) {
            const float a2 = alpha[tid] * SQRT_LOG2E;
            s_bp[tid] = make_float4(a2, beta[tid], -a2 * mu[tid], gamma[tid]);
        }
        __syncthreads();

        const int g  = (bid - NMLP) * 8 + warp;   // warp tile 0..16383
        const int b  = g >> 8;
        const int s0 = (g & 255) * 16;
        const float tv0 = t[(size_t)b * SEQ + s0 + gid];
        const float tv1 = t[(size_t)b * SEQ + s0 + gid + 8];
        unsigned long long tp0, tp1;
        asm("mov.b64 %0, {%1, %1};" : "=l"(tp0) : "f"(tv0));
        asm("mov.b64 %0, {%1, %1};" : "=l"(tp1) : "f"(tv1));

        const ulonglong2* bq = (const ulonglong2*)s_bp;

        #pragma unroll
        for (int kc = 0; kc < 4; kc++) {
            const int n0 = kc * 16 + tig * 2;
            const float e00 = ht_eval(tp0, bq[n0]);
            const float e01 = ht_eval(tp0, bq[n0 + 1]);
            const float e10 = ht_eval(tp1, bq[n0]);
            const float e11 = ht_eval(tp1, bq[n0 + 1]);
            const float e02 = ht_eval(tp0, bq[n0 + 8]);
            const float e03 = ht_eval(tp0, bq[n0 + 9]);
            const float e12 = ht_eval(tp1, bq[n0 + 8]);
            const float e13 = ht_eval(tp1, bq[n0 + 9]);
            __half2 A0 = __floats2half2_rn(e00, e01);
            __half2 A1 = __floats2half2_rn(e10, e11);
            __half2 A2 = __floats2half2_rn(e02, e03);
            __half2 A3 = __floats2half2_rn(e12, e13);
            g_ht[(size_t)(g * 4 + kc) * 32 + lane] =
                make_uint4(*(unsigned*)&A0, *(unsigned*)&A1,
                           *(unsigned*)&A2, *(unsigned*)&A3);
        }
    }
}

// ---------------------------------------------------------------------------
// Kernel B: projection. grid(8, BATCH), 256 threads; each warp does 4 tiles
// (amortizing the omega fragment build). Omega as fp16 hi+lo split -> fp32-
// accurate; h fragments are coalesced uint4 loads in exact MMA layout.
// ---------------------------------------------------------------------------
__global__ __launch_bounds__(256)
void proj_b(float* __restrict__ out)
{
    __shared__ __align__(16) float2 s_om[NB * RANK];

    const int tid  = threadIdx.x;
    const int b    = blockIdx.y;
    const int warp = tid >> 5;
    const int lane = tid & 31;
    const int gid  = lane >> 2;
    const int tig  = lane & 3;

    s_om[tid] = g_oms[b * 256 + tid];
    __syncthreads();

    auto omega_at = [&](int k, int c) -> float {
        const float2 v = s_om[k * 4 + (c & 3)];
        return (c < 4) ? v.x : v.y;
    };

    unsigned bhi[4][2], blo[4][2];
    #pragma unroll
    for (int kc = 0; kc < 4; kc++) {
        #pragma unroll
        for (int h = 0; h < 2; h++) {
            const int k0 = kc * 16 + tig * 2 + h * 8;
            const float w0 = omega_at(k0, gid);
            const float w1 = omega_at(k0 + 1, gid);
            __half2 hh = __floats2half2_rn(w0, w1);
            const float2 hf = __half22float2(hh);
            __half2 ll = __floats2half2_rn(w0 - hf.x, w1 - hf.y);
            bhi[kc][h] = *(unsigned*)&hh;
            blo[kc][h] = *(unsigned*)&ll;
        }
    }

    float* ob = out + (size_t)b * (2 * SEQ * RANK);
    const int t0 = (blockIdx.x * 8 + warp) * 4;   // 4 consecutive tiles

    #pragma unroll
    for (int i = 0; i < 4; i++) {
        const int tile = t0 + i;            // 0..255 within b
        const int g = b * 256 + tile;
        float c0 = 0.f, c1 = 0.f, c2 = 0.f, c3 = 0.f;

        #pragma unroll
        for (int kc = 0; kc < 4; kc++) {
            const uint4 av = g_ht[(size_t)(g * 4 + kc) * 32 + lane];
            asm("mma.sync.aligned.m16n8k16.row.col.f32.f16.f16.f32 "
                "{%0,%1,%2,%3}, {%4,%5,%6,%7}, {%8,%9}, {%0,%1,%2,%3};"
                : "+f"(c0), "+f"(c1), "+f"(c2), "+f"(c3)
                : "r"(av.x), "r"(av.y), "r"(av.z), "r"(av.w),
                  "r"(bhi[kc][0]), "r"(bhi[kc][1]));
            asm("mma.sync.aligned.m16n8k16.row.col.f32.f16.f16.f32 "
                "{%0,%1,%2,%3}, {%4,%5,%6,%7}, {%8,%9}, {%0,%1,%2,%3};"
                : "+f"(c0), "+f"(c1), "+f"(c2), "+f"(c3)
                : "r"(av.x), "r"(av.y), "r"(av.z), "r"(av.w),
                  "r"(blo[kc][0]), "r"(blo[kc][1]));
        }

        const int r0 = tile * 16 + gid;
        const int r1 = r0 + 8;
        *(float2*)(ob + (size_t)r0 * 8 + tig * 2) = make_float2(c0, c1);
        *(float2*)(ob + (size_t)r1 * 8 + tig * 2) = make_float2(c2, c3);
    }
}

// ---------------------------------------------------------------------------
// Launch
// ---------------------------------------------------------------------------
extern "C" void kernel_launch(void* const* d_in, const int* in_sizes, int n_in,
                              void* d_out, int out_size)
{
    const float* f     = (const float*)d_in[0];
    const float* t     = (const float*)d_in[1];
    const float* W1    = (const float*)d_in[2];
    const float* b1    = (const float*)d_in[3];
    const float* W2    = (const float*)d_in[4];
    const float* b2    = (const float*)d_in[5];
    const float* W3    = (const float*)d_in[6];
    const float* b3    = (const float*)d_in[7];
    const float* mu    = (const float*)d_in[8];
    const float* alpha = (const float*)d_in[9];
    const float* beta  = (const float*)d_in[10];
    const float* gamma = (const float*)d_in[11];
    float* out = (float*)d_out;

    fused_a<<<NMLP + NHT, 256>>>(f, t, W1, b1, W2, b2, W3, b3,
                                 mu, alpha, beta, gamma);
    proj_b<<<dim3(8, BATCH), 256>>>(out);
}

// round 10
// speedup vs baseline: 1.9434x; 1.0008x over previous
#include <cuda_runtime.h>
#include <cuda_fp16.h>
#include <cstdint>

#define BATCH 64
#define NB    64
#define RANK  4
#define SEQ   4096

// sqrt(log2(e)) — folds natural-exp into a single ex2.approx
#define SQRT_LOG2E 1.2011224087864498f

#define NMLP  128            // MLP blocks (wave-1 resident, use barriers)
#define NHT   2048           // h_t blocks
#define NTILE 16384          // warp tiles: BATCH * SEQ/16

#define KS1 4
#define KS2 8
#define KS3 16
#define OMSZ (BATCH * NB * RANK * 2)   // floats per omega partial

// ---------------------------------------------------------------------------
// Scratch (device globals; no allocation allowed)
// ---------------------------------------------------------------------------
__device__ __align__(16) float  g_h1p[KS1 * BATCH * 512];
__device__ __align__(16) float  g_h2p[KS2 * BATCH * 1024];
__device__ __align__(16) float  g_omp[KS3 * OMSZ];
__device__ __align__(16) float2 g_oms[BATCH * NB * RANK];   // final omega
__device__ __align__(16) uint4  g_ht [NTILE * 128];         // h_t fragments, 32 MB
__device__ unsigned g_bars[4];                               // monotonic barriers

// ---------------------------------------------------------------------------
// Replay-safe monotonic barrier among P co-resident blocks (counter never
// reset; each use consumes exactly P increments, so replays stay aligned).
// ---------------------------------------------------------------------------
__device__ __forceinline__ void sysbar(int i, unsigned P)
{
    __syncthreads();
    if (threadIdx.x == 0) {
        __threadfence();
        const unsigned old = atomicAdd(&g_bars[i], 1u);
        const unsigned target = old - (old % P) + P;
        while (*((volatile unsigned*)&g_bars[i]) < target) __nanosleep(32);
        __threadfence();
    }
    __syncthreads();
}

// ---------------------------------------------------------------------------
// GEMM tile (R5-proven): 64 rows x 64 cols, 256 threads, f32x2 packed
// accumulators, depth-2 prefetch over double-buffered 8-k smem chunks.
// SRC: 0 = Ain param, 1 = g_h1p (sum NPART + relu), 2 = g_h2p (sum + relu)
// DST: 0 = g_h1p[z] (pre-relu), 1 = g_h2p[z], 2 = packed omega partial
// ---------------------------------------------------------------------------
template <int K, int N, int KS, int SRC, int NPART, int DST>
__device__ void gemm_tile(float (&sW)[2][8][64], float (&sA)[2][8][64],
                          const float* __restrict__ Ain,
                          const float* __restrict__ W,
                          const float* __restrict__ bias, int j0, int z)
{
    constexpr int KC  = K / KS;
    constexpr int NCH = KC / 8;
    const int tid = threadIdx.x;
    const int tx  = tid & 15;
    const int ty  = tid >> 4;
    const int k0  = z * KC;

    const bool isW = tid < 128;
    const int w_kk = tid >> 4;
    const int w_c4 = (tid & 15) * 4;
    const int a_i  = tid - 128;
    const int a_b  = a_i >> 1;
    const int a_kq = (a_i & 1) * 4;

    auto load_chunk = [&](int kc) -> float4 {
        if (isW)
            return *(const float4*)(W + (size_t)(k0 + kc + w_kk) * N + j0 + w_c4);
        float4 av;
        if (SRC == 0) {
            av = *(const float4*)(Ain + a_b * K + k0 + kc + a_kq);
        } else {
            const float* base = (SRC == 1) ? g_h1p : g_h2p;
            const float* p0 = base + a_b * K + k0 + kc + a_kq;
            av = *(const float4*)p0;
            #pragma unroll
            for (int p = 1; p < NPART; p++) {
                const float4 pv = *(const float4*)(p0 + p * (BATCH * K));
                av.x += pv.x; av.y += pv.y; av.z += pv.z; av.w += pv.w;
            }
            av.x = fmaxf(av.x, 0.f); av.y = fmaxf(av.y, 0.f);
            av.z = fmaxf(av.z, 0.f); av.w = fmaxf(av.w, 0.f);
        }
        return av;
    };
    auto store_chunk = [&](int buf, float4 v) {
        if (isW) {
            *(float4*)(&sW[buf][w_kk][w_c4]) = v;
        } else {
            sA[buf][a_kq + 0][a_b] = v.x;
            sA[buf][a_kq + 1][a_b] = v.y;
            sA[buf][a_kq + 2][a_b] = v.z;
            sA[buf][a_kq + 3][a_b] = v.w;
        }
    };

    unsigned long long acc2[4][2];
    #pragma unroll
    for (int r = 0; r < 4; r++) { acc2[r][0] = 0ull; acc2[r][1] = 0ull; }

    float4 f0 = load_chunk(0);
    store_chunk(0, f0);
    float4 f1;
    if (NCH > 1) f1 = load_chunk(8);
    __syncthreads();

    for (int c = 0; c < NCH; c++) {
        float4 f2;
        if (c + 2 < NCH) f2 = load_chunk((c + 2) * 8);

        const int buf = c & 1;
        #pragma unroll
        for (int kk = 0; kk < 8; kk++) {
            const ulonglong2 wq = *(const ulonglong2*)(&sW[buf][kk][tx * 4]);
            const float4 av = *(const float4*)(&sA[buf][kk][ty * 4]);
            const float aa[4] = {av.x, av.y, av.z, av.w};
            #pragma unroll
            for (int r = 0; r < 4; r++) {
                unsigned long long ap;
                asm("mov.b64 %0, {%1, %1};" : "=l"(ap) : "f"(aa[r]));
                asm("fma.rn.f32x2 %0, %1, %2, %0;"
                    : "+l"(acc2[r][0]) : "l"(ap), "l"(wq.x));
                asm("fma.rn.f32x2 %0, %1, %2, %0;"
                    : "+l"(acc2[r][1]) : "l"(ap), "l"(wq.y));
            }
        }

        if (c + 1 < NCH) store_chunk((c + 1) & 1, f1);
        __syncthreads();
        f1 = f2;
    }

    float o[4][4];
    #pragma unroll
    for (int r = 0; r < 4; r++) {
        asm("mov.b64 {%0, %1}, %2;" : "=f"(o[r][0]), "=f"(o[r][1]) : "l"(acc2[r][0]));
        asm("mov.b64 {%0, %1}, %2;" : "=f"(o[r][2]), "=f"(o[r][3]) : "l"(acc2[r][1]));
    }
    const int j = j0 + tx * 4;
    if (z == 0) {
        const float4 bv = *(const float4*)(bias + j);
        #pragma unroll
        for (int r = 0; r < 4; r++) {
            o[r][0] += bv.x; o[r][1] += bv.y; o[r][2] += bv.z; o[r][3] += bv.w;
        }
    }
    #pragma unroll
    for (int r = 0; r < 4; r++) {
        const int b = ty * 4 + r;
        if (DST == 0) {
            *(float4*)(g_h1p + z * (BATCH * 512) + b * 512 + j) =
                make_float4(o[r][0], o[r][1], o[r][2], o[r][3]);
        } else if (DST == 1) {
            *(float4*)(g_h2p + z * (BATCH * 1024) + b * 1024 + j) =
                make_float4(o[r][0], o[r][1], o[r][2], o[r][3]);
        } else {
            const int side = (j >= 256) ? 1 : 0;
            const int n    = (j - side * 256) >> 2;
            float* dst = g_omp + z * OMSZ + ((b * NB + n) * RANK) * 2 + side;
            dst[0] = o[r][0]; dst[2] = o[r][1];
            dst[4] = o[r][2]; dst[6] = o[r][3];
        }
    }
}

// ---------------------------------------------------------------------------
// h_t evaluation: one fma.rn.f32x2 gives {u, w}, then ex2 + cos + mul.
// s_bp per n: float4(a2, beta, -a2*mu, gamma).
// ---------------------------------------------------------------------------
__device__ __forceinline__ float ht_eval(unsigned long long tp, ulonglong2 q)
{
    unsigned long long uw;
    asm("fma.rn.f32x2 %0, %1, %2, %3;" : "=l"(uw) : "l"(tp), "l"(q.x), "l"(q.y));
    float u, w;
    asm("mov.b64 {%0, %1}, %2;" : "=f"(u), "=f"(w) : "l"(uw));
    const float nv = -u * u;
    float e, c;
    asm("ex2.approx.f32 %0, %1;" : "=f"(e) : "f"(nv));
    asm("cos.approx.f32 %0, %1;" : "=f"(c) : "f"(w));
    return e * c;
}

// ---------------------------------------------------------------------------
// Kernel A: fused MLP (blocks 0..NMLP-1, barrier-synced) + h_t fragment
// production (blocks NMLP.., fp16, MMA A-fragment order) — concurrent.
// ---------------------------------------------------------------------------
__global__ void __launch_bounds__(256, 2)
fused_a(const float* __restrict__ f,  const float* __restrict__ t,
        const float* __restrict__ W1, const float* __restrict__ b1,
        const float* __restrict__ W2, const float* __restrict__ b2,
        const float* __restrict__ W3, const float* __restrict__ b3,
        const float* __restrict__ mu, const float* __restrict__ alpha,
        const float* __restrict__ beta, const float* __restrict__ gamma)
{
    __shared__ __align__(16) float  sW[2][8][64];
    __shared__ __align__(16) float  sA[2][8][64];
    __shared__ __align__(16) float4 s_bp[NB];

    const int bid = blockIdx.x;
    const int tid = threadIdx.x;

    if (bid < NMLP) {
        // ---------------- fused MLP ----------------
        if (bid < 8 * KS1)   // 32 tiles: j0 x z
            gemm_tile<128, 512, KS1, 0, 1, 0>(sW, sA, f, W1, b1,
                                              (bid & 7) * 64, bid >> 3);
        sysbar(0, NMLP);
        // 16 col-tiles x KS2=8 = 128 units
        gemm_tile<512, 1024, KS2, 1, KS1, 1>(sW, sA, nullptr, W2, b2,
                                             (bid & 15) * 64, bid >> 4);
        sysbar(1, NMLP);
        // 8 col-tiles x KS3=16 = 128 units
        gemm_tile<1024, 512, KS3, 2, KS2, 2>(sW, sA, nullptr, W3, b3,
                                             (bid & 7) * 64, bid >> 3);
        sysbar(2, NMLP);
        if (bid < 32) {   // omega reduce: 8192 float4 over 32*256 threads
            const float4* src = (const float4*)g_omp;
            float4* dst = (float4*)g_oms;
            const int e = bid * 256 + tid;
            float4 a = src[e];
            #pragma unroll
            for (int p = 1; p < KS3; p++) {
                const float4 v = src[p * (OMSZ / 4) + e];
                a.x += v.x; a.y += v.y; a.z += v.z; a.w += v.w;
            }
            dst[e] = a;
        }
    } else {
        // ---------------- h_t fragments ----------------
        const int warp = tid >> 5;
        const int lane = tid & 31;
        const int gid  = lane >> 2;
        const int tig  = lane & 3;

        if (tid < NB) {
            const float a2 = alpha[tid] * SQRT_LOG2E;
            s_bp[tid] = make_float4(a2, beta[tid], -a2 * mu[tid], gamma[tid]);
        }
        __syncthreads();

        const int g  = (bid - NMLP) * 8 + warp;   // warp tile 0..16383
        const int b  = g >> 8;
        const int s0 = (g & 255) * 16;
        const float tv0 = t[(size_t)b * SEQ + s0 + gid];
        const float tv1 = t[(size_t)b * SEQ + s0 + gid + 8];
        unsigned long long tp0, tp1;
        asm("mov.b64 %0, {%1, %1};" : "=l"(tp0) : "f"(tv0));
        asm("mov.b64 %0, {%1, %1};" : "=l"(tp1) : "f"(tv1));

        const ulonglong2* bq = (const ulonglong2*)s_bp;

        #pragma unroll
        for (int kc = 0; kc < 4; kc++) {
            const int n0 = kc * 16 + tig * 2;
            const float e00 = ht_eval(tp0, bq[n0]);
            const float e01 = ht_eval(tp0, bq[n0 + 1]);
            const float e10 = ht_eval(tp1, bq[n0]);
            const float e11 = ht_eval(tp1, bq[n0 + 1]);
            const float e02 = ht_eval(tp0, bq[n0 + 8]);
            const float e03 = ht_eval(tp0, bq[n0 + 9]);
            const float e12 = ht_eval(tp1, bq[n0 + 8]);
            const float e13 = ht_eval(tp1, bq[n0 + 9]);
            __half2 A0 = __floats2half2_rn(e00, e01);
            __half2 A1 = __floats2half2_rn(e10, e11);
            __half2 A2 = __floats2half2_rn(e02, e03);
            __half2 A3 = __floats2half2_rn(e12, e13);
            g_ht[(size_t)(g * 4 + kc) * 32 + lane] =
                make_uint4(*(unsigned*)&A0, *(unsigned*)&A1,
                           *(unsigned*)&A2, *(unsigned*)&A3);
        }
    }
}

// ---------------------------------------------------------------------------
// Kernel B: projection. grid(8, BATCH), 256 threads; each warp does 4 tiles
// (amortizing the omega fragment build). Omega as fp16 hi+lo split -> fp32-
// accurate; h fragments are coalesced uint4 loads in exact MMA layout.
// ---------------------------------------------------------------------------
__global__ __launch_bounds__(256)
void proj_b(float* __restrict__ out)
{
    __shared__ __align__(16) float2 s_om[NB * RANK];

    const int tid  = threadIdx.x;
    const int b    = blockIdx.y;
    const int warp = tid >> 5;
    const int lane = tid & 31;
    const int gid  = lane >> 2;
    const int tig  = lane & 3;

    s_om[tid] = g_oms[b * 256 + tid];
    __syncthreads();

    auto omega_at = [&](int k, int c) -> float {
        const float2 v = s_om[k * 4 + (c & 3)];
        return (c < 4) ? v.x : v.y;
    };

    unsigned bhi[4][2], blo[4][2];
    #pragma unroll
    for (int kc = 0; kc < 4; kc++) {
        #pragma unroll
        for (int h = 0; h < 2; h++) {
            const int k0 = kc * 16 + tig * 2 + h * 8;
            const float w0 = omega_at(k0, gid);
            const float w1 = omega_at(k0 + 1, gid);
            __half2 hh = __floats2half2_rn(w0, w1);
            const float2 hf = __half22float2(hh);
            __half2 ll = __floats2half2_rn(w0 - hf.x, w1 - hf.y);
            bhi[kc][h] = *(unsigned*)&hh;
            blo[kc][h] = *(unsigned*)&ll;
        }
    }

    float* ob = out + (size_t)b * (2 * SEQ * RANK);
    const int t0 = (blockIdx.x * 8 + warp) * 4;   // 4 consecutive tiles

    #pragma unroll
    for (int i = 0; i < 4; i++) {
        const int tile = t0 + i;            // 0..255 within b
        const int g = b * 256 + tile;
        float c0 = 0.f, c1 = 0.f, c2 = 0.f, c3 = 0.f;

        #pragma unroll
        for (int kc = 0; kc < 4; kc++) {
            const uint4 av = g_ht[(size_t)(g * 4 + kc) * 32 + lane];
            asm("mma.sync.aligned.m16n8k16.row.col.f32.f16.f16.f32 "
                "{%0,%1,%2,%3}, {%4,%5,%6,%7}, {%8,%9}, {%0,%1,%2,%3};"
                : "+f"(c0), "+f"(c1), "+f"(c2), "+f"(c3)
                : "r"(av.x), "r"(av.y), "r"(av.z), "r"(av.w),
                  "r"(bhi[kc][0]), "r"(bhi[kc][1]));
            asm("mma.sync.aligned.m16n8k16.row.col.f32.f16.f16.f32 "
                "{%0,%1,%2,%3}, {%4,%5,%6,%7}, {%8,%9}, {%0,%1,%2,%3};"
                : "+f"(c0), "+f"(c1), "+f"(c2), "+f"(c3)
                : "r"(av.x), "r"(av.y), "r"(av.z), "r"(av.w),
                  "r"(blo[kc][0]), "r"(blo[kc][1]));
        }

        const int r0 = tile * 16 + gid;
        const int r1 = r0 + 8;
        *(float2*)(ob + (size_t)r0 * 8 + tig * 2) = make_float2(c0, c1);
        *(float2*)(ob + (size_t)r1 * 8 + tig * 2) = make_float2(c2, c3);
    }
}

// ---------------------------------------------------------------------------
// Launch
// ---------------------------------------------------------------------------
extern "C" void kernel_launch(void* const* d_in, const int* in_sizes, int n_in,
                              void* d_out, int out_size)
{
    const float* f     = (const float*)d_in[0];
    const float* t     = (const float*)d_in[1];
    const float* W1    = (const float*)d_in[2];
    const float* b1    = (const float*)d_in[3];
    const float* W2    = (const float*)d_in[4];
    const float* b2    = (const float*)d_in[5];
    const float* W3    = (const float*)d_in[6];
    const float* b3    = (const float*)d_in[7];
    const float* mu    = (const float*)d_in[8];
    const float* alpha = (const float*)d_in[9];
    const float* beta  = (const float*)d_in[10];
    const float* gamma = (const float*)d_in[11];
    float* out = (float*)d_out;

    fused_a<<<NMLP + NHT, 256>>>(f, t, W1, b1, W2, b2, W3, b3,
                                 mu, alpha, beta, gamma);
    proj_b<<<dim3(8, BATCH), 256>>>(out);
}